// round 1
// baseline (speedup 1.0000x reference)
#include <cuda_runtime.h>

// Problem constants
#define BB   8
#define SS   1024
#define FEAT 1024
#define HIDD 1024
#define HH   8
#define DHH  128
#define MTOT (BB * SS)   // 8192

__device__ float g_Q[MTOT * HIDD];
__device__ float g_K[MTOT * HIDD];
__device__ float g_V[MTOT * HIDD];

// ---------------------------------------------------------------------------
// QKV projection: C = A[M,K] @ W[K,N] + bias, one of Q/K/V per blockIdx.z.
// 128x128 tile, BK=8, 256 threads, 8x8 register micro-tile.
// ---------------------------------------------------------------------------
__global__ __launch_bounds__(256)
void qkv_gemm_kernel(const float* __restrict__ A,
                     const float* __restrict__ Wq, const float* __restrict__ bq,
                     const float* __restrict__ Wk, const float* __restrict__ bk,
                     const float* __restrict__ Wv, const float* __restrict__ bv)
{
    __shared__ float As[8][132];
    __shared__ float Ws[8][132];

    const float* Wm;
    const float* bias;
    float* C;
    if (blockIdx.z == 0)      { Wm = Wq; bias = bq; C = g_Q; }
    else if (blockIdx.z == 1) { Wm = Wk; bias = bk; C = g_K; }
    else                      { Wm = Wv; bias = bv; C = g_V; }

    const int tid = threadIdx.x;
    const int tx = tid & 15;
    const int ty = tid >> 4;
    const int row0 = blockIdx.y * 128;
    const int col0 = blockIdx.x * 128;

    const int arow = tid >> 1;
    const int acol = (tid & 1) * 4;
    const int wrow = tid >> 5;
    const int wcol = (tid & 31) * 4;

    float acc[8][8];
#pragma unroll
    for (int i = 0; i < 8; i++)
#pragma unroll
        for (int j = 0; j < 8; j++) acc[i][j] = 0.0f;

    const float* Aptr = A + (long)(row0 + arow) * FEAT + acol;
    const float* Wptr = Wm + (long)wrow * HIDD + col0 + wcol;

    for (int k0 = 0; k0 < FEAT; k0 += 8) {
        float4 av = *(const float4*)(Aptr + k0);
        float4 wv = *(const float4*)(Wptr + (long)k0 * HIDD);
        As[acol + 0][arow] = av.x;
        As[acol + 1][arow] = av.y;
        As[acol + 2][arow] = av.z;
        As[acol + 3][arow] = av.w;
        *(float4*)&Ws[wrow][wcol] = wv;
        __syncthreads();

#pragma unroll
        for (int kk = 0; kk < 8; kk++) {
            float a[8], w[8];
            *(float4*)&a[0] = *(const float4*)&As[kk][ty * 8];
            *(float4*)&a[4] = *(const float4*)&As[kk][ty * 8 + 4];
            *(float4*)&w[0] = *(const float4*)&Ws[kk][tx * 8];
            *(float4*)&w[4] = *(const float4*)&Ws[kk][tx * 8 + 4];
#pragma unroll
            for (int i = 0; i < 8; i++)
#pragma unroll
                for (int j = 0; j < 8; j++)
                    acc[i][j] += a[i] * w[j];
        }
        __syncthreads();
    }

    float4 b0 = *(const float4*)&bias[col0 + tx * 8];
    float4 b1 = *(const float4*)&bias[col0 + tx * 8 + 4];
#pragma unroll
    for (int i = 0; i < 8; i++) {
        float* crow = C + (long)(row0 + ty * 8 + i) * HIDD + col0 + tx * 8;
        float4 o0, o1;
        o0.x = acc[i][0] + b0.x; o0.y = acc[i][1] + b0.y;
        o0.z = acc[i][2] + b0.z; o0.w = acc[i][3] + b0.w;
        o1.x = acc[i][4] + b1.x; o1.y = acc[i][5] + b1.y;
        o1.z = acc[i][6] + b1.z; o1.w = acc[i][7] + b1.w;
        *(float4*)&crow[0] = o0;
        *(float4*)&crow[4] = o1;
    }
}

// ---------------------------------------------------------------------------
// Attention: per (b,h, q-tile of 64). Flash-style online softmax over the
// double-exp score y = exp(qk/sqrt(DH)) with causal hard-mask (soft -128 mask
// is numerically indistinguishable from hard mask for these magnitudes).
// ---------------------------------------------------------------------------
#define QROW_STR 132   // padded row stride for 128-wide tiles
#define PROW_STR 68    // padded row stride for 64-wide score tile
#define SMEM_ATTN_FLOATS (3 * 64 * QROW_STR + 64 * PROW_STR + 3 * 64)

__global__ __launch_bounds__(256)
void attn_kernel(float* __restrict__ out)
{
    extern __shared__ float sm[];
    float* Qs  = sm;                        // [64][132]
    float* Ks  = Qs + 64 * QROW_STR;        // [64][132]
    float* Vs  = Ks + 64 * QROW_STR;        // [64][132]
    float* Ps  = Vs + 64 * QROW_STR;        // [64][68]
    float* m_s = Ps + 64 * PROW_STR;        // [64]
    float* l_s = m_s + 64;                  // [64]
    float* c_s = l_s + 64;                  // [64]

    const int tid = threadIdx.x;
    const int tx = tid & 15;   // 16 groups: k-dir (4 cols) / d-dir (8 cols)
    const int ty = tid >> 4;   // 16 groups: q-dir (4 rows)
    const int bh = blockIdx.y;
    const int b = bh >> 3;
    const int h = bh & 7;
    const int qt = blockIdx.x;
    const int q0 = qt * 64;

    const float inv_sqrt_dh = 0.08838834764831843f;  // 1/sqrt(128)

    const float* Qg = g_Q + (long)b * SS * HIDD + h * DHH;
    const float* Kg = g_K + (long)b * SS * HIDD + h * DHH;
    const float* Vg = g_V + (long)b * SS * HIDD + h * DHH;

    // load Q tile [64 x 128]
    for (int i = tid; i < 64 * 32; i += 256) {
        int r = i >> 5;
        int c = (i & 31) * 4;
        *(float4*)&Qs[r * QROW_STR + c] =
            *(const float4*)&Qg[(long)(q0 + r) * HIDD + c];
    }
    if (tid < 64) { m_s[tid] = -1e30f; l_s[tid] = 0.0f; }

    float O[4][8];
#pragma unroll
    for (int i = 0; i < 4; i++)
#pragma unroll
        for (int j = 0; j < 8; j++) O[i][j] = 0.0f;

    __syncthreads();

    for (int kt = 0; kt <= qt; kt++) {
        const int k0 = kt * 64;
        // load K,V tiles [64 x 128]
        for (int i = tid; i < 64 * 32; i += 256) {
            int r = i >> 5;
            int c = (i & 31) * 4;
            *(float4*)&Ks[r * QROW_STR + c] =
                *(const float4*)&Kg[(long)(k0 + r) * HIDD + c];
            *(float4*)&Vs[r * QROW_STR + c] =
                *(const float4*)&Vg[(long)(k0 + r) * HIDD + c];
        }
        __syncthreads();

        // S tile: s[i][j] = Q[ty*4+i] . K[tx*4+j]
        float s[4][4];
#pragma unroll
        for (int i = 0; i < 4; i++)
#pragma unroll
            for (int j = 0; j < 4; j++) s[i][j] = 0.0f;

        for (int d = 0; d < DHH; d += 4) {
            float4 qa[4], kb[4];
#pragma unroll
            for (int i = 0; i < 4; i++)
                qa[i] = *(const float4*)&Qs[(ty * 4 + i) * QROW_STR + d];
#pragma unroll
            for (int j = 0; j < 4; j++)
                kb[j] = *(const float4*)&Ks[(tx * 4 + j) * QROW_STR + d];
#pragma unroll
            for (int i = 0; i < 4; i++)
#pragma unroll
                for (int j = 0; j < 4; j++) {
                    s[i][j] += qa[i].x * kb[j].x;
                    s[i][j] += qa[i].y * kb[j].y;
                    s[i][j] += qa[i].z * kb[j].z;
                    s[i][j] += qa[i].w * kb[j].w;
                }
        }

        // y = exp(logits); causal hard mask (k > q => -inf)
#pragma unroll
        for (int i = 0; i < 4; i++) {
            int qg = q0 + ty * 4 + i;
#pragma unroll
            for (int j = 0; j < 4; j++) {
                int kg = k0 + tx * 4 + j;
                float y = __expf(s[i][j] * inv_sqrt_dh);
                if (kg > qg) y = -1e30f;
                Ps[(ty * 4 + i) * PROW_STR + tx * 4 + j] = y;
            }
        }
        __syncthreads();

        // per-row online softmax update (one thread per q-row)
        if (tid < 64) {
            float* prow = Ps + tid * PROW_STR;
            float mo = m_s[tid];
            float mn = mo;
#pragma unroll 8
            for (int j = 0; j < 64; j++) mn = fmaxf(mn, prow[j]);
            float corr = __expf(mo - mn);
            float l = l_s[tid] * corr;
#pragma unroll 8
            for (int j = 0; j < 64; j++) {
                float p = __expf(prow[j] - mn);
                prow[j] = p;
                l += p;
            }
            m_s[tid] = mn;
            l_s[tid] = l;
            c_s[tid] = corr;
        }
        __syncthreads();

        // O = O * corr + P @ V
        float corr[4];
#pragma unroll
        for (int i = 0; i < 4; i++) corr[i] = c_s[ty * 4 + i];
#pragma unroll
        for (int i = 0; i < 4; i++)
#pragma unroll
            for (int j = 0; j < 8; j++) O[i][j] *= corr[i];

        for (int k = 0; k < 64; k++) {
            float p[4];
#pragma unroll
            for (int i = 0; i < 4; i++) p[i] = Ps[(ty * 4 + i) * PROW_STR + k];
            float4 v0 = *(const float4*)&Vs[k * QROW_STR + tx * 8];
            float4 v1 = *(const float4*)&Vs[k * QROW_STR + tx * 8 + 4];
#pragma unroll
            for (int i = 0; i < 4; i++) {
                O[i][0] += p[i] * v0.x;
                O[i][1] += p[i] * v0.y;
                O[i][2] += p[i] * v0.z;
                O[i][3] += p[i] * v0.w;
                O[i][4] += p[i] * v1.x;
                O[i][5] += p[i] * v1.y;
                O[i][6] += p[i] * v1.z;
                O[i][7] += p[i] * v1.w;
            }
        }
        __syncthreads();
    }

    // normalize and write [B,S,HID]
    float linv[4];
#pragma unroll
    for (int i = 0; i < 4; i++) linv[i] = 1.0f / l_s[ty * 4 + i];

    float* outp = out + (long)b * SS * HIDD + h * DHH;
#pragma unroll
    for (int i = 0; i < 4; i++) {
        float4 o0, o1;
        o0.x = O[i][0] * linv[i]; o0.y = O[i][1] * linv[i];
        o0.z = O[i][2] * linv[i]; o0.w = O[i][3] * linv[i];
        o1.x = O[i][4] * linv[i]; o1.y = O[i][5] * linv[i];
        o1.z = O[i][6] * linv[i]; o1.w = O[i][7] * linv[i];
        float* orow = outp + (long)(q0 + ty * 4 + i) * HIDD + tx * 8;
        *(float4*)&orow[0] = o0;
        *(float4*)&orow[4] = o1;
    }
}

// ---------------------------------------------------------------------------
extern "C" void kernel_launch(void* const* d_in, const int* in_sizes, int n_in,
                              void* d_out, int out_size)
{
    const float* queries = (const float*)d_in[0];
    const float* Wq = (const float*)d_in[1];
    const float* bq = (const float*)d_in[2];
    const float* Wk = (const float*)d_in[3];
    const float* bk = (const float*)d_in[4];
    const float* Wv = (const float*)d_in[5];
    const float* bv = (const float*)d_in[6];
    float* out = (float*)d_out;

    dim3 g1(HIDD / 128, MTOT / 128, 3);
    qkv_gemm_kernel<<<g1, 256>>>(queries, Wq, bq, Wk, bk, Wv, bv);

    const int smem_attn = SMEM_ATTN_FLOATS * (int)sizeof(float);
    cudaFuncSetAttribute(attn_kernel,
                         cudaFuncAttributeMaxDynamicSharedMemorySize, smem_attn);
    dim3 g2(SS / 64, BB * HH);
    attn_kernel<<<g2, 256, smem_attn>>>(out);
}

// round 2
// speedup vs baseline: 4.4927x; 4.4927x over previous
#include <cuda_runtime.h>
#include <cstdint>

#define BB 8
#define SS 1024
#define FEAT 1024
#define HIDD 1024
#define HH 8
#define DHH 128
#define MTOT (BB*SS)

// tf32-rounded copies (bit patterns stored as uint32)
__device__ uint32_t g_Ar[MTOT*FEAT];
__device__ uint32_t g_W0[FEAT*HIDD];
__device__ uint32_t g_W1[FEAT*HIDD];
__device__ uint32_t g_W2[FEAT*HIDD];
__device__ uint32_t g_Q[MTOT*HIDD];
__device__ uint32_t g_K[MTOT*HIDD];
__device__ uint32_t g_V[MTOT*HIDD];

__device__ __forceinline__ uint32_t f2t(float x) {
    uint32_t u;
    asm("cvt.rna.tf32.f32 %0, %1;" : "=r"(u) : "f"(x));
    return u;
}
__device__ __forceinline__ uint32_t smaddr(const void* p) {
    return (uint32_t)__cvta_generic_to_shared(p);
}

#define CP16(dst,src) asm volatile("cp.async.cg.shared.global [%0], [%1], 16;" :: "r"(dst), "l"(src))
#define CPCOMMIT()    asm volatile("cp.async.commit_group;")
#define CPWAIT(n)     asm volatile("cp.async.wait_group %0;" :: "n"(n))

__device__ __forceinline__ void mma8(float* d, const uint32_t* a, const uint32_t* b) {
    asm volatile(
        "mma.sync.aligned.m16n8k8.row.col.f32.tf32.tf32.f32 "
        "{%0,%1,%2,%3}, {%4,%5,%6,%7}, {%8,%9}, {%0,%1,%2,%3};"
        : "+f"(d[0]), "+f"(d[1]), "+f"(d[2]), "+f"(d[3])
        : "r"(a[0]), "r"(a[1]), "r"(a[2]), "r"(a[3]), "r"(b[0]), "r"(b[1]));
}

// ---------------------------------------------------------------------------
// Pass 0: round inputs to tf32 (rna) once, so the GEMM can move raw bits.
// ---------------------------------------------------------------------------
__global__ __launch_bounds__(256)
void round_kernel(const float4* __restrict__ A, const float4* __restrict__ W0,
                  const float4* __restrict__ W1, const float4* __restrict__ W2)
{
    const int NA = MTOT*FEAT/4;   // 2097152
    const int NW = FEAT*HIDD/4;   // 262144
    int i = blockIdx.x*256 + threadIdx.x;
    if (i < NA) {
        float4 v = A[i];
        ((uint4*)g_Ar)[i] = make_uint4(f2t(v.x), f2t(v.y), f2t(v.z), f2t(v.w));
        return;
    }
    i -= NA;
    if (i < NW) {
        float4 v = W0[i];
        ((uint4*)g_W0)[i] = make_uint4(f2t(v.x), f2t(v.y), f2t(v.z), f2t(v.w));
        return;
    }
    i -= NW;
    if (i < NW) {
        float4 v = W1[i];
        ((uint4*)g_W1)[i] = make_uint4(f2t(v.x), f2t(v.y), f2t(v.z), f2t(v.w));
        return;
    }
    i -= NW;
    if (i < NW) {
        float4 v = W2[i];
        ((uint4*)g_W2)[i] = make_uint4(f2t(v.x), f2t(v.y), f2t(v.z), f2t(v.w));
    }
}

// ---------------------------------------------------------------------------
// Pass 1: QKV projection GEMM, tf32 mma.sync.
// Block 128 threads (4 warps, 64x64 each), block tile 128x128, K-step 32,
// cp.async double-buffered smem. Epilogue adds bias and stores tf32 bits.
// ---------------------------------------------------------------------------
#define AS_STR 36
#define WS_STR 132
#define AS_SZ (128*AS_STR)    // words
#define WS_SZ (32*WS_STR)
#define STG   (AS_SZ + WS_SZ) // 8832 words
#define GSM_BYTES (2*STG*4)   // 70656

__global__ __launch_bounds__(128)
void qkv_mma_kernel(const float* __restrict__ bq, const float* __restrict__ bk,
                    const float* __restrict__ bv)
{
    extern __shared__ uint32_t smg[];
    const int tid = threadIdx.x;
    const int w = tid >> 5, lane = tid & 31;
    const int g = lane >> 2, t = lane & 3;
    const int mw = (w >> 1) * 64, nw = (w & 1) * 64;
    const int row0 = blockIdx.y * 128, col0 = blockIdx.x * 128;

    const uint32_t* Wg = (blockIdx.z == 0) ? g_W0 : (blockIdx.z == 1 ? g_W1 : g_W2);
    const float* bias  = (blockIdx.z == 0) ? bq  : (blockIdx.z == 1 ? bk  : bv);
    uint32_t* Og       = (blockIdx.z == 0) ? g_Q : (blockIdx.z == 1 ? g_K : g_V);

    float acc[4][8][4];
#pragma unroll
    for (int i = 0; i < 4; i++)
#pragma unroll
        for (int j = 0; j < 8; j++)
#pragma unroll
            for (int e = 0; e < 4; e++) acc[i][j][e] = 0.0f;

    auto issue = [&](int it) {
        int st = it & 1;
        uint32_t base = smaddr(smg + st*STG);
        int k0 = it * 32;
#pragma unroll
        for (int c = 0; c < 8; c++) {
            int slot = tid + c*128;            // 0..1023
            int r = slot >> 3, kc = (slot & 7) * 4;
            CP16(base + (r*AS_STR + kc)*4, g_Ar + (long)(row0 + r)*FEAT + k0 + kc);
        }
        uint32_t baseW = base + AS_SZ*4;
#pragma unroll
        for (int c = 0; c < 8; c++) {
            int slot = tid + c*128;
            int r = slot >> 5, nc = (slot & 31) * 4;
            CP16(baseW + (r*WS_STR + nc)*4, Wg + (long)(k0 + r)*HIDD + col0 + nc);
        }
    };

    issue(0); CPCOMMIT();
    for (int it = 0; it < 32; ++it) {
        if (it + 1 < 32) issue(it + 1);
        CPCOMMIT();
        CPWAIT(1);
        __syncthreads();
        const uint32_t* As = smg + (it & 1)*STG;
        const uint32_t* Ws = As + AS_SZ;
#pragma unroll
        for (int ks = 0; ks < 4; ks++) {
            uint32_t a[4][4], bfr[8][2];
#pragma unroll
            for (int i = 0; i < 4; i++) {
                const uint32_t* ap = As + (mw + i*16 + g)*AS_STR + ks*8 + t;
                a[i][0] = ap[0];
                a[i][1] = ap[8*AS_STR];
                a[i][2] = ap[4];
                a[i][3] = ap[8*AS_STR + 4];
            }
#pragma unroll
            for (int j = 0; j < 8; j++) {
                const uint32_t* bp = Ws + (ks*8 + t)*WS_STR + nw + j*8 + g;
                bfr[j][0] = bp[0];
                bfr[j][1] = bp[4*WS_STR];
            }
#pragma unroll
            for (int i = 0; i < 4; i++)
#pragma unroll
                for (int j = 0; j < 8; j++)
                    mma8(acc[i][j], a[i], bfr[j]);
        }
        __syncthreads();
    }

    // epilogue: + bias, round to tf32, store bits
#pragma unroll
    for (int j = 0; j < 8; j++) {
        int col = col0 + nw + j*8 + 2*t;
        float b0 = bias[col], b1 = bias[col + 1];
#pragma unroll
        for (int i = 0; i < 4; i++) {
            int row = row0 + mw + i*16 + g;
            uint2 v0 = make_uint2(f2t(acc[i][j][0] + b0), f2t(acc[i][j][1] + b1));
            uint2 v1 = make_uint2(f2t(acc[i][j][2] + b0), f2t(acc[i][j][3] + b1));
            *(uint2*)(Og + (long)row*HIDD + col) = v0;
            *(uint2*)(Og + (long)(row + 8)*HIDD + col) = v1;
        }
    }
}

// ---------------------------------------------------------------------------
// Pass 2: causal attention, tf32 mma.sync, flash-style without online max
// (y = exp(logit) <= ~13, exp(y) <= ~5e5, row sums < 2^31 -> no overflow;
//  masked entries carry weight exp(y-128) ~ 1e-52 -> exactly droppable).
// Block: 128 threads (4 warps x 16 q-rows), q-tile 64, k-tile 64.
// ---------------------------------------------------------------------------
#define KV_STR 132
#define PS_STR 68
#define ASM_BYTES ((2*64*KV_STR + 64*PS_STR)*4)   // 84992

__global__ __launch_bounds__(128)
void attn_kernel(float* __restrict__ out)
{
    extern __shared__ uint32_t sm[];
    uint32_t* Ks = sm;
    uint32_t* Vs = sm + 64*KV_STR;
    uint32_t* Ps = sm + 2*64*KV_STR;

    const int tid = threadIdx.x;
    const int w = tid >> 5, lane = tid & 31;
    const int g = lane >> 2, t = lane & 3;
    const int m0 = w * 16;
    const int qt = blockIdx.x, q0 = qt * 64;
    const int bh = blockIdx.y, b = bh >> 3, h = bh & 7;

    const uint32_t* Qg = g_Q + (long)b*SS*HIDD + h*DHH;
    const uint32_t* Kg = g_K + (long)b*SS*HIDD + h*DHH;
    const uint32_t* Vg = g_V + (long)b*SS*HIDD + h*DHH;

    // stage Q tile through Ks, pull A-fragments into registers
    {
        uint32_t base = smaddr(Ks);
#pragma unroll
        for (int c = 0; c < 16; c++) {
            int slot = tid + c*128;            // 0..2047
            int r = slot >> 5, cc = (slot & 31) * 4;
            CP16(base + (r*KV_STR + cc)*4, Qg + (long)(q0 + r)*HIDD + cc);
        }
        CPCOMMIT(); CPWAIT(0);
    }
    __syncthreads();

    uint32_t aQ[16][4];
#pragma unroll
    for (int ks = 0; ks < 16; ks++) {
        const uint32_t* qp = Ks + (m0 + g)*KV_STR + ks*8 + t;
        aQ[ks][0] = qp[0];
        aQ[ks][1] = qp[8*KV_STR];
        aQ[ks][2] = qp[4];
        aQ[ks][3] = qp[8*KV_STR + 4];
    }
    __syncthreads();

    float accO[16][4];
#pragma unroll
    for (int j = 0; j < 16; j++)
#pragma unroll
        for (int e = 0; e < 4; e++) accO[j][e] = 0.0f;
    float l0 = 0.0f, l1 = 0.0f;
    const float scl = 0.08838834764831843f;   // 1/sqrt(128)

    for (int kt = 0; kt <= qt; kt++) {
        const int k0 = kt * 64;
        uint32_t baseK = smaddr(Ks), baseV = smaddr(Vs);
#pragma unroll
        for (int c = 0; c < 16; c++) {
            int slot = tid + c*128;
            int r = slot >> 5, cc = (slot & 31) * 4;
            CP16(baseK + (r*KV_STR + cc)*4, Kg + (long)(k0 + r)*HIDD + cc);
            CP16(baseV + (r*KV_STR + cc)*4, Vg + (long)(k0 + r)*HIDD + cc);
        }
        CPCOMMIT(); CPWAIT(0);
        __syncthreads();

        // S = Q K^T  (per warp: m16 x n64)
        float s[8][4];
#pragma unroll
        for (int j = 0; j < 8; j++)
#pragma unroll
            for (int e = 0; e < 4; e++) s[j][e] = 0.0f;
#pragma unroll
        for (int ks = 0; ks < 16; ks++) {
#pragma unroll
            for (int j = 0; j < 8; j++) {
                uint32_t bfr[2];
                const uint32_t* kp = Ks + (j*8 + g)*KV_STR + ks*8 + t;
                bfr[0] = kp[0];
                bfr[1] = kp[4];
                mma8(s[j], aQ[ks], bfr);
            }
        }

        // p = exp(exp(s/sqrt(d))), diagonal-tile causal mask, accumulate l
        const bool diag = (kt == qt);
        const int row_g  = q0 + m0 + g;
        const int row_g8 = row_g + 8;
#pragma unroll
        for (int j = 0; j < 8; j++) {
            int c0 = k0 + j*8 + 2*t;
            float y0 = __expf(s[j][0]*scl), y1 = __expf(s[j][1]*scl);
            float y2 = __expf(s[j][2]*scl), y3 = __expf(s[j][3]*scl);
            float p0 = __expf(y0), p1 = __expf(y1);
            float p2 = __expf(y2), p3 = __expf(y3);
            if (diag) {
                if (c0     > row_g ) p0 = 0.0f;
                if (c0 + 1 > row_g ) p1 = 0.0f;
                if (c0     > row_g8) p2 = 0.0f;
                if (c0 + 1 > row_g8) p3 = 0.0f;
            }
            uint32_t u0 = f2t(p0), u1 = f2t(p1), u2 = f2t(p2), u3 = f2t(p3);
            l0 += __uint_as_float(u0) + __uint_as_float(u1);
            l1 += __uint_as_float(u2) + __uint_as_float(u3);
            *(uint2*)(Ps + (m0 + g)*PS_STR + j*8 + 2*t)     = make_uint2(u0, u1);
            *(uint2*)(Ps + (m0 + g + 8)*PS_STR + j*8 + 2*t) = make_uint2(u2, u3);
        }
        __syncthreads();

        // O += P V  (per warp: m16 x n128)
#pragma unroll
        for (int ks = 0; ks < 8; ks++) {
            uint32_t aP[4];
            const uint32_t* pp = Ps + (m0 + g)*PS_STR + ks*8 + t;
            aP[0] = pp[0];
            aP[1] = pp[8*PS_STR];
            aP[2] = pp[4];
            aP[3] = pp[8*PS_STR + 4];
#pragma unroll
            for (int j = 0; j < 16; j++) {
                uint32_t bfr[2];
                const uint32_t* vp = Vs + (ks*8 + t)*KV_STR + j*8 + g;
                bfr[0] = vp[0];
                bfr[1] = vp[4*KV_STR];
                mma8(accO[j], aP, bfr);
            }
        }
        __syncthreads();
    }

    // row-sum reduce across the quad, normalize, store
    l0 += __shfl_xor_sync(0xffffffffu, l0, 1);
    l0 += __shfl_xor_sync(0xffffffffu, l0, 2);
    l1 += __shfl_xor_sync(0xffffffffu, l1, 1);
    l1 += __shfl_xor_sync(0xffffffffu, l1, 2);
    const float r0 = 1.0f / l0, r1 = 1.0f / l1;

    float* outp = out + ((long)b*SS + q0 + m0 + g)*HIDD + h*DHH;
#pragma unroll
    for (int j = 0; j < 16; j++) {
        int col = j*8 + 2*t;
        *(float2*)(outp + col)            = make_float2(accO[j][0]*r0, accO[j][1]*r0);
        *(float2*)(outp + 8*HIDD + col)   = make_float2(accO[j][2]*r1, accO[j][3]*r1);
    }
}

// ---------------------------------------------------------------------------
extern "C" void kernel_launch(void* const* d_in, const int* in_sizes, int n_in,
                              void* d_out, int out_size)
{
    const float* queries = (const float*)d_in[0];
    const float* Wq = (const float*)d_in[1];
    const float* bq = (const float*)d_in[2];
    const float* Wk = (const float*)d_in[3];
    const float* bk = (const float*)d_in[4];
    const float* Wv = (const float*)d_in[5];
    const float* bv = (const float*)d_in[6];
    float* out = (float*)d_out;

    cudaFuncSetAttribute(qkv_mma_kernel, cudaFuncAttributeMaxDynamicSharedMemorySize, GSM_BYTES);
    cudaFuncSetAttribute(attn_kernel, cudaFuncAttributeMaxDynamicSharedMemorySize, ASM_BYTES);

    round_kernel<<<11264, 256>>>((const float4*)queries, (const float4*)Wq,
                                 (const float4*)Wk, (const float4*)Wv);
    qkv_mma_kernel<<<dim3(8, 64, 3), 128, GSM_BYTES>>>(bq, bk, bv);
    attn_kernel<<<dim3(16, 64), 128, ASM_BYTES>>>(out);
}